// round 17
// baseline (speedup 1.0000x reference)
#include <cuda_runtime.h>
#include <cuda_fp16.h>
#include <math.h>
#include <stdint.h>

#define Bq 8
#define Nq 1024
#define Cq 512
#define Hq 4
#define HDq 128
#define SCALEq 0.08838834764831845f

// ---------------- scratch ----------------
__device__ __half g_q[Bq * Hq * Nq * HDq];
__device__ __half g_k[Bq * Hq * Nq * HDq];
__device__ __half g_v[Bq * Hq * Nq * HDq];
__device__ float  g_s[(size_t)Bq * Hq * Nq * Nq];   // scores TRANSPOSED: S_t[z][m][n]
__device__ __half g_y[Bq * Nq * Cq];
__device__ __half g_x[Bq * Nq * Cq];
__device__ __half g_wq[3 * Cq * Cq];
__device__ __half g_wp[Cq * Cq];

// ---------------- helpers ----------------
__device__ __forceinline__ uint32_t smem_u32(const void* p) {
    uint32_t a;
    asm("{ .reg .u64 t; cvta.to.shared.u64 t, %1; cvt.u32.u64 %0, t; }" : "=r"(a) : "l"(p));
    return a;
}
__device__ __forceinline__ void cpa16(uint32_t dst, const void* src) {
    asm volatile("cp.async.ca.shared.global [%0], [%1], 16;" :: "r"(dst), "l"(src));
}
#define CP_COMMIT() asm volatile("cp.async.commit_group;")
#define CP_WAIT(n)  asm volatile("cp.async.wait_group %0;" :: "n"(n))

__device__ __forceinline__ void ldsm4(uint32_t& r0, uint32_t& r1, uint32_t& r2, uint32_t& r3,
                                      uint32_t addr) {
    asm volatile("ldmatrix.sync.aligned.m8n8.x4.shared.b16 {%0,%1,%2,%3}, [%4];"
                 : "=r"(r0), "=r"(r1), "=r"(r2), "=r"(r3) : "r"(addr));
}
__device__ __forceinline__ void ldsm4t(uint32_t& r0, uint32_t& r1, uint32_t& r2, uint32_t& r3,
                                       uint32_t addr) {
    asm volatile("ldmatrix.sync.aligned.m8n8.x4.trans.shared.b16 {%0,%1,%2,%3}, [%4];"
                 : "=r"(r0), "=r"(r1), "=r"(r2), "=r"(r3) : "r"(addr));
}
__device__ __forceinline__ void mma16(float c[4], const uint32_t a[4], uint32_t b0, uint32_t b1) {
    asm volatile(
        "mma.sync.aligned.m16n8k16.row.col.f32.f16.f16.f32 "
        "{%0,%1,%2,%3},{%4,%5,%6,%7},{%8,%9},{%0,%1,%2,%3};"
        : "+f"(c[0]), "+f"(c[1]), "+f"(c[2]), "+f"(c[3])
        : "r"(a[0]), "r"(a[1]), "r"(a[2]), "r"(a[3]), "r"(b0), "r"(b1));
}

// BK=64 GEMM cores. A/B abt smem row: 64 halfs + 8 pad = 144 B.
#define RSA 144
#define ABUF 18432   // 128*144

// ===== core: C(128x128) = A(128xK) * B(128xK)^T, fp16 K-major, 128 thr, BK=64 =====
template <int K>
__device__ __forceinline__ void hgemm_abt(const __half* __restrict__ A, int lda,
                                          const __half* __restrict__ B, int ldb,
                                          float c[4][8][4]) {
    extern __shared__ __align__(16) char smem_dyn[];
    char* sA = smem_dyn;
    char* sB = smem_dyn + 2 * ABUF;
    const int tid = threadIdx.x, lane = tid & 31, wid = tid >> 5;
    const int wm = (wid & 1) * 64, wn = (wid >> 1) * 64;
    const uint32_t sbA = smem_u32(sA), sbB = smem_u32(sB);
    const uint32_t aBase = sbA + (uint32_t)((wm + (lane & 7) + ((lane >> 3) & 1) * 8) * RSA
                                            + (lane >> 4) * 16);
    const uint32_t bBase = sbB + (uint32_t)((wn + (lane & 7) + (lane >> 4) * 8) * RSA
                                            + ((lane >> 3) & 1) * 16);

    auto issue = [&](int buf, int k0) {
        const uint32_t bA = sbA + buf * ABUF;
        const uint32_t bB = sbB + buf * ABUF;
#pragma unroll
        for (int i = 0; i < 8; i++) {
            int ch = tid + i * 128;
            int r = ch >> 3, c16 = (ch & 7) * 16;
            cpa16(bA + r * RSA + c16, (const char*)(A + (size_t)r * lda + k0) + c16);
            cpa16(bB + r * RSA + c16, (const char*)(B + (size_t)r * ldb + k0) + c16);
        }
        CP_COMMIT();
    };

    constexpr int NS = K / 64;
    issue(0, 0);
#pragma unroll 1
    for (int s = 0; s < NS; s++) {
        CP_WAIT(0);
        __syncthreads();
        if (s + 1 < NS) issue((s + 1) & 1, (s + 1) * 64);
        const uint32_t off = (s & 1) * ABUF;
#pragma unroll
        for (int kk = 0; kk < 4; kk++) {
            uint32_t a[4][4], b[4][4];
#pragma unroll
            for (int t = 0; t < 4; t++)
                ldsm4(a[t][0], a[t][1], a[t][2], a[t][3], aBase + off + t * (16 * RSA) + kk * 32);
#pragma unroll
            for (int du = 0; du < 4; du++)
                ldsm4(b[du][0], b[du][1], b[du][2], b[du][3], bBase + off + du * (16 * RSA) + kk * 32);
#pragma unroll
            for (int t = 0; t < 4; t++)
#pragma unroll
                for (int du = 0; du < 4; du++) {
                    mma16(c[t][du * 2 + 0], a[t], b[du][0], b[du][1]);
                    mma16(c[t][du * 2 + 1], a[t], b[du][2], b[du][3]);
                }
        }
    }
}

// ---------------- kernels ----------------

__global__ void k_round16(const float* __restrict__ src, __half* __restrict__ dst, int n4) {
    int i = blockIdx.x * blockDim.x + threadIdx.x;
    if (i >= n4) return;
    float4 v = ((const float4*)src)[i];
    ((__half2*)dst)[2 * i]     = __floats2half2_rn(v.x, v.y);
    ((__half2*)dst)[2 * i + 1] = __floats2half2_rn(v.z, v.w);
}

// qkv = x @ w_qkv^T ; scatter fp16 into g_q/g_k/g_v [b,h,n,d]
__global__ void __launch_bounds__(128, 2) k_qkv() {
    const int row0 = blockIdx.y * 128;
    const int col0 = blockIdx.x * 128;
    float c[4][8][4] = {};
    hgemm_abt<Cq>(g_x + (size_t)row0 * Cq, Cq, g_wq + (size_t)col0 * Cq, Cq, c);

    const int part = col0 >> 9;
    const int h = (col0 & 511) >> 7;
    __half* dst = (part == 0) ? g_q : (part == 1) ? g_k : g_v;

    const int tid = threadIdx.x, lane = tid & 31, wid = tid >> 5;
    const int wm = (wid & 1) * 64, wn = (wid >> 1) * 64;
    const int lr = lane >> 2, lc = lane & 3;
#pragma unroll
    for (int t = 0; t < 4; t++)
#pragma unroll
        for (int u = 0; u < 8; u++) {
            const int d = wn + u * 8 + 2 * lc;
#pragma unroll
            for (int half = 0; half < 2; half++) {
                const int r = row0 + wm + t * 16 + lr + half * 8;
                const int b = r >> 10, n = r & 1023;
                __half* p = dst + ((size_t)((b * Hq + h) * Nq + n)) * HDq + d;
                *(__half2*)p = __floats2half2_rn(c[t][u][half * 2 + 0], c[t][u][half * 2 + 1]);
            }
        }
}

// S_t[z][m][n] = q_n . k_m  (TRANSPOSED store; scale folded into mix later)
__global__ void __launch_bounds__(128, 2) k_scores() {
    const int z = blockIdx.z;
    const int row0 = blockIdx.y * 128;   // n (query)
    const int col0 = blockIdx.x * 128;   // m (key)
    float c[4][8][4] = {};
    const __half* A = g_q + (size_t)z * Nq * HDq + (size_t)row0 * HDq;
    const __half* B = g_k + (size_t)z * Nq * HDq + (size_t)col0 * HDq;
    hgemm_abt<HDq>(A, HDq, B, HDq, c);

    float* St = g_s + (size_t)z * Nq * Nq;
    const int tid = threadIdx.x, lane = tid & 31, wid = tid >> 5;
    const int wm = (wid & 1) * 64, wn = (wid >> 1) * 64;
    const int lr = lane >> 2, lc = lane & 3;
#pragma unroll
    for (int t = 0; t < 4; t++)
#pragma unroll
        for (int u = 0; u < 8; u++) {
            const int m = col0 + wn + u * 8 + 2 * lc;
#pragma unroll
            for (int half = 0; half < 2; half++) {
                const int n = row0 + wm + t * 16 + lr + half * 8;
                St[(size_t)m * Nq + n]       = c[t][u][half * 2 + 0];
                St[(size_t)(m + 1) * Nq + n] = c[t][u][half * 2 + 1];
            }
        }
}

// ================= fused mix + online-softmax + PV =================
// CTA: (b, 64-query block), all 4 heads. 256 threads = 8 warps;
// warp pair (wid>>1)=head i; warp (wid&1) owns d-half. Loop 32-key blocks.
// S tiles arrive TRANSPOSED [m][n] (row 288 B) -> conflict-free lane-n reads.
#define MSP_S_ROW   288
#define MSP_S_OFF   0            // [2][4][32 m][288]  S_t tiles f32
#define MSP_S_H     9216
#define MSP_S_BUF   36864
#define MSP_V_OFF   73728        // [2][4][32][272]  V tiles fp16
#define MSP_V_BUF   34816
#define MSP_V_H     8704
#define MSP_P_OFF   143360       // [4][64][80]      probs fp16
#define MSP_P_H     5120
#define MSP_M_OFF   163840       // [4][64] f32 running max
#define MSP_L_OFF   164864       // [4][64] f32 running sum
#define MSP_R_OFF   165888       // [4][64] f32 row scale this stage
#define MSP_SMEM    166912

__global__ void __launch_bounds__(256, 1)
k_msp(const float* __restrict__ w_main, const float* __restrict__ w_rest) {
    extern __shared__ __align__(16) char sm[];
    const int tid = threadIdx.x, lane = tid & 31, wid = tid >> 5;
    const int b = blockIdx.y;
    const int n0 = blockIdx.x * 64;
    const int i = wid >> 1;               // head of this warp pair
    const int dhalf = (wid & 1) * 64;     // d range of this warp
    const int lane_g = (wid & 1) * 32 + lane;  // row 0..63 within pair
    const uint32_t sb = smem_u32(sm);

    float* sm_m = (float*)(sm + MSP_M_OFF);
    float* sm_l = (float*)(sm + MSP_L_OFF);
    float* sm_r = (float*)(sm + MSP_R_OFF);

    float Mi[Hq];
#pragma unroll
    for (int j = 0; j < Hq; j++)
        Mi[j] = ((j == i) ? w_main[i] : w_rest[i * (Hq - 1) + j - (j > i ? 1 : 0)]) * SCALEq;

    sm_m[tid] = -INFINITY;
    sm_l[tid] = 0.f;

    // cp.async issue for stage (keys m0..m0+31) into buf
    auto issue = [&](int buf, int m0) {
        const uint32_t bS = sb + MSP_S_OFF + buf * MSP_S_BUF;
        const uint32_t bV = sb + MSP_V_OFF + buf * MSP_V_BUF;
#pragma unroll
        for (int k = 0; k < 8; k++) {                 // S_t: 4h x 32m x 16 chunks = 2048
            int ch = tid + k * 256;
            int h = ch >> 9, r = (ch >> 4) & 31, c16 = (ch & 15) * 16;
            const char* src = (const char*)g_s
                + ((((size_t)(b * Hq + h) * Nq + m0 + r) * Nq + n0) << 2) + c16;
            cpa16(bS + h * MSP_S_H + r * MSP_S_ROW + c16, src);
        }
#pragma unroll
        for (int k = 0; k < 8; k++) {                 // V: 2048 chunks
            int ch = tid + k * 256;
            int h = ch >> 9, r = (ch >> 4) & 31, c16 = (ch & 15) * 16;
            const char* src = (const char*)g_v
                + ((((size_t)(b * Hq + h) * Nq + m0 + r) * HDq) << 1) + c16;
            cpa16(bV + h * MSP_V_H + r * 272 + c16, src);
        }
        CP_COMMIT();
    };

    // ldsm bases
    const uint32_t aBase = sb + MSP_P_OFF + i * MSP_P_H
        + (uint32_t)(((lane & 7) + ((lane >> 3) & 1) * 8) * 80 + (lane >> 4) * 16);
    const uint32_t btBase0 = sb + MSP_V_OFF + i * MSP_V_H
        + (uint32_t)(((lane & 7) + ((lane >> 3) & 1) * 8) * 272
                     + (dhalf + (lane >> 4) * 8) * 2);

    float c[4][8][4] = {};

    issue(0, 0);
    __syncthreads();

#pragma unroll 1
    for (int s = 0; s < 32; s++) {
        CP_WAIT(0);
        __syncthreads();
        if (s + 1 < 32) issue((s + 1) & 1, (s + 1) * 32);

        // ---- probs phase: lane owns row n = lane_g of head i; conflict-free ----
        {
            const int n = lane_g;
            float L[32];
#pragma unroll
            for (int m = 0; m < 32; m++) L[m] = 0.f;
#pragma unroll
            for (int h = 0; h < Hq; h++) {
                const char* sp = sm + MSP_S_OFF + (s & 1) * MSP_S_BUF + h * MSP_S_H + n * 4;
                const float mh = Mi[h];
#pragma unroll
                for (int m = 0; m < 32; m++)
                    L[m] += mh * *(const float*)(sp + m * MSP_S_ROW);
            }
            float bm = L[0];
#pragma unroll
            for (int m = 1; m < 32; m++) bm = fmaxf(bm, L[m]);
            const float m_old = sm_m[i * 64 + n];
            const float m_new = fmaxf(m_old, bm);
            const float scale = __expf(m_old - m_new);
            float psum = 0.f;
            __half2* pp = (__half2*)(sm + MSP_P_OFF + i * MSP_P_H + n * 80);
#pragma unroll
            for (int m = 0; m < 16; m++) {
                float p0 = __expf(L[2 * m + 0] - m_new);
                float p1 = __expf(L[2 * m + 1] - m_new);
                psum += p0 + p1;
                pp[m] = __floats2half2_rn(p0, p1);
            }
            sm_m[i * 64 + n] = m_new;
            sm_l[i * 64 + n] = sm_l[i * 64 + n] * scale + psum;
            sm_r[i * 64 + n] = scale;
        }
        __syncthreads();

        // ---- MMA phase: rescale O, then O += P_i * V_i ----
        {
            const int lr = lane >> 2;
#pragma unroll
            for (int t = 0; t < 4; t++)
#pragma unroll
                for (int half = 0; half < 2; half++) {
                    const float sc = sm_r[i * 64 + t * 16 + lr + half * 8];
#pragma unroll
                    for (int u = 0; u < 8; u++) {
                        c[t][u][half * 2 + 0] *= sc;
                        c[t][u][half * 2 + 1] *= sc;
                    }
                }
            const uint32_t btBase = btBase0 + (s & 1) * MSP_V_BUF;
#pragma unroll
            for (int kk = 0; kk < 2; kk++) {
                uint32_t a[4][4], bfr[4][4];
#pragma unroll
                for (int t = 0; t < 4; t++)
                    ldsm4(a[t][0], a[t][1], a[t][2], a[t][3], aBase + t * (16 * 80) + kk * 32);
#pragma unroll
                for (int du = 0; du < 4; du++)
                    ldsm4t(bfr[du][0], bfr[du][1], bfr[du][2], bfr[du][3],
                           btBase + kk * (16 * 272) + du * 32);
#pragma unroll
                for (int t = 0; t < 4; t++)
#pragma unroll
                    for (int du = 0; du < 4; du++) {
                        mma16(c[t][du * 2 + 0], a[t], bfr[du][0], bfr[du][1]);
                        mma16(c[t][du * 2 + 1], a[t], bfr[du][2], bfr[du][3]);
                    }
            }
        }
        __syncthreads();
    }

    // ---- epilogue: O /= l, write fp16 to g_y[b, n, i*128 + d] ----
    {
        const int lr = lane >> 2, lc = lane & 3;
#pragma unroll
        for (int t = 0; t < 4; t++)
#pragma unroll
            for (int half = 0; half < 2; half++) {
                const int row = t * 16 + lr + half * 8;
                const float inv = 1.f / sm_l[i * 64 + row];
                const int n = n0 + row;
#pragma unroll
                for (int u = 0; u < 8; u++) {
                    const int d = dhalf + u * 8 + 2 * lc;
                    __half* p = g_y + ((size_t)b * Nq + n) * Cq + i * HDq + d;
                    *(__half2*)p = __floats2half2_rn(c[t][u][half * 2 + 0] * inv,
                                                     c[t][u][half * 2 + 1] * inv);
                }
            }
    }
}

// out = y @ w_proj^T + b_proj (f32 out)
__global__ void __launch_bounds__(128, 2)
k_proj(const float* __restrict__ bias, float* __restrict__ out) {
    const int row0 = blockIdx.y * 128;
    const int col0 = blockIdx.x * 128;
    float c[4][8][4] = {};
    hgemm_abt<Cq>(g_y + (size_t)row0 * Cq, Cq, g_wp + (size_t)col0 * Cq, Cq, c);

    const int tid = threadIdx.x, lane = tid & 31, wid = tid >> 5;
    const int wm = (wid & 1) * 64, wn = (wid >> 1) * 64;
    const int lr = lane >> 2, lc = lane & 3;
#pragma unroll
    for (int t = 0; t < 4; t++)
#pragma unroll
        for (int u = 0; u < 8; u++) {
            const int col = col0 + wn + u * 8 + 2 * lc;
            const float b0 = bias[col], b1 = bias[col + 1];
#pragma unroll
            for (int half = 0; half < 2; half++) {
                const int r = row0 + wm + t * 16 + lr + half * 8;
                *(float2*)(out + (size_t)r * Cq + col) =
                    make_float2(c[t][u][half * 2 + 0] + b0, c[t][u][half * 2 + 1] + b1);
            }
        }
}

// ---------------- launch ----------------
extern "C" void kernel_launch(void* const* d_in, const int* in_sizes, int n_in,
                              void* d_out, int out_size) {
    const float* x      = (const float*)d_in[0];
    const float* w_qkv  = (const float*)d_in[1];
    const float* w_proj = (const float*)d_in[2];
    const float* b_proj = (const float*)d_in[3];
    const float* w_main = (const float*)d_in[4];
    const float* w_rest = (const float*)d_in[5];
    float* out = (float*)d_out;

    __half* p_x;  cudaGetSymbolAddress((void**)&p_x,  g_x);
    __half* p_wq; cudaGetSymbolAddress((void**)&p_wq, g_wq);
    __half* p_wp; cudaGetSymbolAddress((void**)&p_wp, g_wp);

    const int dynSmem = 4 * ABUF;   // 73728 B for abt cores
    cudaFuncSetAttribute(k_qkv,    cudaFuncAttributeMaxDynamicSharedMemorySize, dynSmem);
    cudaFuncSetAttribute(k_scores, cudaFuncAttributeMaxDynamicSharedMemorySize, dynSmem);
    cudaFuncSetAttribute(k_proj,   cudaFuncAttributeMaxDynamicSharedMemorySize, dynSmem);
    cudaFuncSetAttribute(k_msp,    cudaFuncAttributeMaxDynamicSharedMemorySize, MSP_SMEM);

    {
        int n4 = Bq * Nq * Cq / 4;
        k_round16<<<(n4 + 255) / 256, 256>>>(x, p_x, n4);
        n4 = 3 * Cq * Cq / 4;
        k_round16<<<(n4 + 255) / 256, 256>>>(w_qkv, p_wq, n4);
        n4 = Cq * Cq / 4;
        k_round16<<<(n4 + 255) / 256, 256>>>(w_proj, p_wp, n4);
    }
    k_qkv<<<dim3(1536 / 128, (Bq * Nq) / 128), 128, dynSmem>>>();
    k_scores<<<dim3(Nq / 128, Nq / 128, Bq * Hq), 128, dynSmem>>>();
    k_msp<<<dim3(Nq / 64, Bq), 256, MSP_SMEM>>>(w_main, w_rest);
    k_proj<<<dim3(Cq / 128, (Bq * Nq) / 128), 128, dynSmem>>>(b_proj, out);
}